// round 11
// baseline (speedup 1.0000x reference)
#include <cuda_runtime.h>
#include <cstdint>

#define BB 16
#define NN 1024
#define DD 64
#define FIN 80
#define BN_EPS 1e-5f

typedef unsigned long long ull;

// ---------------- scratch globals -------------------------------------------
__device__ float    g_h[BB*NN*DD];          // node features fp32
__device__ float    g_hW[BB*NN*DD];         // relu(h @ Wl)
__device__ float2   g_t1e1[BB*NN];          // (t1, exp(t1))
__device__ float2   g_te2[BB*NN];           // (t2, exp(t2))
__device__ unsigned g_adjT[BB*32*NN];       // transposed bitmask [b][word][n]
__device__ float    g_Sall3[3*BB*DD];       // per-layer column sums of hW
__device__ int      g_idx[3*BB*NN];         // active-row indices per (layer,b)
__device__ int      g_cnt[3*BB];            // active-row counts
__device__ float    g_nP[2*BB*NN*DD];       // m-split partial numerators
__device__ float    g_zP[2*BB*NN];          // m-split partial Z
__device__ int      g_tilecnt[3*BB*8];      // per-tile arrival counters

// ---------------- packed f32x2 helpers --------------------------------------
__device__ __forceinline__ ull pack2(float x, float y) {
    ull r;
    asm("mov.b64 %0, {%1, %2};" : "=l"(r) : "f"(x), "f"(y));
    return r;
}
__device__ __forceinline__ void unpack2(ull v, float &x, float &y) {
    asm("mov.b64 {%0, %1}, %2;" : "=f"(x), "=f"(y) : "l"(v));
}
__device__ __forceinline__ void ffma2(ull &d, ull a, ull b) {
    asm("fma.rn.f32x2 %0, %1, %2, %0;" : "+l"(d) : "l"(a), "l"(b));
}
__device__ __forceinline__ ull addf2(ull a, ull b) {
    ull r;
    asm("add.rn.f32x2 %0, %1, %2;" : "=l"(r) : "l"(a), "l"(b));
    return r;
}

// ---------------- kernel 0: compact active rows per (layer, b) --------------
__global__ void __launch_bounds__(32) compact_kernel(const float* __restrict__ root_list,
                                                     int pair0) {
    int pair = pair0 + blockIdx.x;         // li*16 + b
    int li = pair >> 4, b = pair & 15;
    int lane = threadIdx.x;
    int rootLayer = 3 - li;
    const float* r = root_list + b * (4 * NN) + rootLayer * NN;
    int* idx = g_idx + (size_t)pair * NN;
    if (lane < 8) g_tilecnt[pair * 8 + lane] = 0;
    int cnt = 0;
    for (int c = 0; c < 32; ++c) {
        int n = c * 32 + lane;
        bool a = r[n] > 0.f;
        unsigned m = __ballot_sync(0xffffffffu, a);
        int pos = cnt + __popc(m & ((1u << lane) - 1u));
        if (a) idx[pos] = n;
        cnt += __popc(m);
    }
    for (int i = cnt + lane; i < NN; i += 32) idx[i] = 0;
    if (lane == 0) g_cnt[pair] = cnt;
}

// ---------------- kernel 1: pack adj (transposed bitmask) + zero Sall -------
__global__ void __launch_bounds__(256) pack_adj_kernel(const int* __restrict__ adj) {
    __shared__ unsigned tw[32 * 64];       // [word][n_local]
    int b  = blockIdx.x >> 4;
    int nt = blockIdx.x & 15;
    int tid = threadIdx.x;
    int w   = tid >> 5;
    int lane = tid & 31;

    if (blockIdx.x == 0) {
        for (int i = tid; i < 3 * BB * DD; i += 256) g_Sall3[i] = 0.f;
    }

    for (int j = 0; j < 8; ++j) {
        int nl = w * 8 + j;
        const int* rowp = adj + ((size_t)(b * NN + nt * 64 + nl)) * NN;
        #pragma unroll 4
        for (int c = 0; c < 32; ++c) {
            int v = rowp[c * 32 + lane];
            unsigned m = __ballot_sync(0xffffffffu, v > 0);
            if (lane == 0) tw[c * 64 + nl] = m;
        }
    }
    __syncthreads();
    for (int i = tid; i < 2048; i += 256) {
        int c = i >> 6, nl = i & 63;
        g_adjT[(size_t)(b * 32 + c) * NN + nt * 64 + nl] = tw[i];
    }
}

// ---------------- kernel 2: h = relu(X @ W0), 2 CTAs/SM ----------------------
__global__ void __launch_bounds__(256, 2) input_proj_kernel(const float* __restrict__ X,
                                                            const float* __restrict__ W0) {
    __shared__ float  xs[64 * FIN];
    __shared__ float2 wp[FIN * 32];
    int tid = threadIdx.x;
    int rowbase = blockIdx.x * 64;

    const float4* xsrc = (const float4*)(X + (size_t)rowbase * FIN);
    float4* xdst = (float4*)xs;
    #pragma unroll
    for (int t = 0; t < 5; ++t) xdst[tid + t * 256] = xsrc[tid + t * 256];

    for (int idx = tid; idx < FIN * 32; idx += 256) {
        int k = idx >> 5, l = idx & 31;
        wp[idx] = make_float2(W0[k * 64 + l], W0[k * 64 + l + 32]);
    }
    __syncthreads();

    int w = tid >> 5, lane = tid & 31;
    for (int j = 0; j < 8; ++j) {
        int row = w * 8 + j;
        const float* xr = xs + row * FIN;
        float a0 = 0.f, a1 = 0.f;
        #pragma unroll
        for (int k = 0; k < FIN; k += 4) {
            float4 x4 = *(const float4*)(xr + k);
            float2 w0 = wp[(k + 0) * 32 + lane];
            float2 w1 = wp[(k + 1) * 32 + lane];
            float2 w2 = wp[(k + 2) * 32 + lane];
            float2 w3 = wp[(k + 3) * 32 + lane];
            a0 = fmaf(x4.x, w0.x, a0); a1 = fmaf(x4.x, w0.y, a1);
            a0 = fmaf(x4.y, w1.x, a0); a1 = fmaf(x4.y, w1.y, a1);
            a0 = fmaf(x4.z, w2.x, a0); a1 = fmaf(x4.z, w2.y, a1);
            a0 = fmaf(x4.w, w3.x, a0); a1 = fmaf(x4.w, w3.y, a1);
        }
        int gr = rowbase + row;
        g_h[gr * 64 + lane]      = fmaxf(a0, 0.f);
        g_h[gr * 64 + lane + 32] = fmaxf(a1, 0.f);
    }
}

// ---- kernel 3: hW = relu(h@Wl); t1/t2/exp; Sall; 2 CTAs/SM -----------------
__global__ void __launch_bounds__(256, 2) hw_kernel(const float* __restrict__ Wl,
                                                    const float* __restrict__ a1l,
                                                    const float* __restrict__ a2l,
                                                    int li) {
    __shared__ float  hs[64 * 64];
    __shared__ float2 wp[64 * 32];
    __shared__ float2 pt[64 * 9];
    int tid = threadIdx.x;
    int rowbase = blockIdx.x * 64;
    int b = rowbase >> 10;

    const float4* hsrc = (const float4*)(g_h + (size_t)rowbase * 64);
    float4* hdst = (float4*)hs;
    #pragma unroll
    for (int t = 0; t < 4; ++t) hdst[tid + t * 256] = hsrc[tid + t * 256];

    const float* W = Wl + li * 4096;
    for (int idx = tid; idx < 2048; idx += 256) {
        int k = idx >> 5, l = idx & 31;
        wp[idx] = make_float2(W[k * 64 + l], W[k * 64 + l + 32]);
    }
    __syncthreads();

    int w = tid >> 5, lane = tid & 31;
    float a1lo = a1l[li * 64 + lane], a1hi = a1l[li * 64 + lane + 32];
    float a2lo = a2l[li * 64 + lane], a2hi = a2l[li * 64 + lane + 32];
    float s0 = 0.f, s1 = 0.f;

    #pragma unroll
    for (int jg = 0; jg < 4; ++jg) {
        int row0 = w * 8 + jg * 2;
        const float* hr0 = hs + (row0 + 0) * 64;
        const float* hr1 = hs + (row0 + 1) * 64;
        float acc[2][2];
        acc[0][0] = 0.f; acc[0][1] = 0.f;
        acc[1][0] = 0.f; acc[1][1] = 0.f;

        #pragma unroll
        for (int k = 0; k < 64; k += 4) {
            float2 w0 = wp[(k + 0) * 32 + lane];
            float2 w1 = wp[(k + 1) * 32 + lane];
            float2 w2 = wp[(k + 2) * 32 + lane];
            float2 w3 = wp[(k + 3) * 32 + lane];
            float4 h0 = *(const float4*)(hr0 + k);
            float4 h1 = *(const float4*)(hr1 + k);
            acc[0][0] = fmaf(h0.x, w0.x, acc[0][0]); acc[0][1] = fmaf(h0.x, w0.y, acc[0][1]);
            acc[0][0] = fmaf(h0.y, w1.x, acc[0][0]); acc[0][1] = fmaf(h0.y, w1.y, acc[0][1]);
            acc[0][0] = fmaf(h0.z, w2.x, acc[0][0]); acc[0][1] = fmaf(h0.z, w2.y, acc[0][1]);
            acc[0][0] = fmaf(h0.w, w3.x, acc[0][0]); acc[0][1] = fmaf(h0.w, w3.y, acc[0][1]);
            acc[1][0] = fmaf(h1.x, w0.x, acc[1][0]); acc[1][1] = fmaf(h1.x, w0.y, acc[1][1]);
            acc[1][0] = fmaf(h1.y, w1.x, acc[1][0]); acc[1][1] = fmaf(h1.y, w1.y, acc[1][1]);
            acc[1][0] = fmaf(h1.z, w2.x, acc[1][0]); acc[1][1] = fmaf(h1.z, w2.y, acc[1][1]);
            acc[1][0] = fmaf(h1.w, w3.x, acc[1][0]); acc[1][1] = fmaf(h1.w, w3.y, acc[1][1]);
        }

        #pragma unroll
        for (int r = 0; r < 2; ++r) {
            float acc0 = fmaxf(acc[r][0], 0.f);
            float acc1 = fmaxf(acc[r][1], 0.f);
            int row = row0 + r;
            int gr = rowbase + row;
            g_hW[gr * 64 + lane]      = acc0;
            g_hW[gr * 64 + lane + 32] = acc1;
            s0 += acc0; s1 += acc1;

            float p1 = fmaf(acc1, a1hi, acc0 * a1lo);
            float p2 = fmaf(acc1, a2hi, acc0 * a2lo);
            p1 += __shfl_down_sync(0xffffffffu, p1, 16);
            p2 += __shfl_down_sync(0xffffffffu, p2, 16);
            p1 += __shfl_down_sync(0xffffffffu, p1, 8);
            p2 += __shfl_down_sync(0xffffffffu, p2, 8);
            if (lane < 8) pt[row * 9 + lane] = make_float2(p1, p2);
        }
    }
    float* sall = g_Sall3 + li * (BB * DD);
    atomicAdd(&sall[b * 64 + lane],      s0);
    atomicAdd(&sall[b * 64 + lane + 32], s1);

    __syncthreads();
    if (tid < 64) {
        int row = tid;
        float p1 = 0.f, p2 = 0.f;
        #pragma unroll
        for (int k = 0; k < 8; ++k) {
            float2 q = pt[row * 9 + k];
            p1 += q.x; p2 += q.y;
        }
        int gr = rowbase + row;
        g_t1e1[gr] = make_float2(p1, __expf(p1));
        g_te2[gr]  = make_float2(p2, __expf(p2));
    }
}

// ---------------- kernel 4: compacted + m-split attention (FFMA2, 8n x 8d) --
// Fused: parallel cross-group reduction + last-arriver combine (no epi kernel).
#define SM_COEF   0          // f32[4][2][32*128] = 131072 (also acc dump: 4x32KB)
#define SM_HWP    131072     // f32[4][2][32*64]  = 65536
#define SM_TE     196608     // float2[512]       = 4096
#define SM_T1E1   204800     // float2[128]       = 1024
#define SM_IDX    205824     // int[128]          = 512
#define SM_Z      206592     // f32[4][128]       = 2048
#define SM_ATTN_TOTAL 208640

__global__ void __launch_bounds__(512, 1) attn_kernel(int li) {
    extern __shared__ char smem[];
    float*  coef_s = (float*)(smem + SM_COEF);
    float*  hwp_s  = (float*)(smem + SM_HWP);
    float2* te_s   = (float2*)(smem + SM_TE);
    float2* t1e1_s = (float2*)(smem + SM_T1E1);
    int*    idx_s  = (int*)(smem + SM_IDX);
    float*  z_s    = (float*)(smem + SM_Z);
    __shared__ int sh_who;

    int tid = threadIdx.x;
    int bx  = blockIdx.x;
    int b   = bx >> 4;
    int nt  = (bx >> 1) & 7;
    int ms  = bx & 1;
    int nbase = nt * 128;
    int pair = li * 16 + b;
    int cnt = g_cnt[pair];
    if (nbase >= cnt) return;

    int gid = tid >> 7;                  // m-group 0..3
    int wt  = tid & 127;                 // thread within group
    int nq = wt >> 3;                    // 0..15 -> n rows nq*8..+7
    int dq = wt & 7;                     // 0..7  -> d cols dq*8..+7

    const float4*   hwbase = (const float4*)(g_hW + (size_t)b * NN * DD);
    const float2*   te_g   = g_te2 + b * NN;
    const unsigned* awcol  = g_adjT + (size_t)b * 32 * NN;

    int ri = g_idx[(size_t)pair * NN + nbase + wt];

    // ---- prefetch chunk 0 of this group ----
    unsigned pf_aw;
    float4 pf_hw[4];
    {
        int c = ms * 16 + gid * 4;
        pf_aw = awcol[(size_t)c * NN + ri];
        #pragma unroll
        for (int t = 0; t < 4; ++t) {
            int i = wt + t * 128;
            pf_hw[t] = hwbase[(c * 32 + (i >> 4)) * 16 + (i & 15)];
        }
    }

    // ---- CTA-wide staging ----
    te_s[tid] = te_g[ms * 512 + tid];
    if (tid < 128) {
        idx_s[tid]  = ri;
        t1e1_s[tid] = g_t1e1[b * NN + ri];
    }
    __syncthreads();

    float zpart = 0.f;

    // stage+gen chunk 0 into buf 0
    {
        float* hb = hwp_s + (gid * 2 + 0) * 2048;
        #pragma unroll
        for (int t = 0; t < 4; ++t) {
            int i = wt + t * 128;
            int m = i >> 4, d16 = i & 15;
            *(float4*)(hb + m * 64 + (d16 & 1) * 32 + (d16 >> 1) * 4) = pf_hw[t];
        }
        float* cb = coef_s + (gid * 2 + 0) * 4096;
        float2 t1e1 = t1e1_s[wt];
        int lc = gid * 4;
        #pragma unroll 8
        for (int m = 0; m < 32; ++m) {
            float2 te = te_s[lc * 32 + m];
            bool p = ((pf_aw >> m) & 1u) && (t1e1.x + te.x > 0.f);
            float cf = p ? fmaf(t1e1.y, te.y, -1.f) : 0.f;
            zpart += cf;
            cb[m * 128 + wt] = cf;
        }
    }
    asm volatile("bar.sync %0, %1;" :: "r"(gid + 1), "r"(128) : "memory");

    ull acc[32];
    #pragma unroll
    for (int i = 0; i < 32; ++i) acc[i] = 0ull;

    #pragma unroll 1
    for (int cg = 0; cg < 4; ++cg) {
        int buf = cg & 1;

        if (cg < 3) {
            int c = ms * 16 + gid * 4 + cg + 1;
            pf_aw = awcol[(size_t)c * NN + idx_s[wt]];
            #pragma unroll
            for (int t = 0; t < 4; ++t) {
                int i = wt + t * 128;
                pf_hw[t] = hwbase[(c * 32 + (i >> 4)) * 16 + (i & 15)];
            }
        }

        // ---- matmul on current buffer ----
        {
            const float* cb = coef_s + (gid * 2 + buf) * 4096;
            const float* hb = hwp_s + (gid * 2 + buf) * 2048;
            #pragma unroll 4
            for (int m = 0; m < 32; ++m) {
                float4 c0 = *(const float4*)(cb + m * 128 + nq * 8);
                float4 c1 = *(const float4*)(cb + m * 128 + nq * 8 + 4);
                ulonglong2 hA = *(const ulonglong2*)(hb + m * 64 + dq * 4);
                ulonglong2 hB = *(const ulonglong2*)(hb + m * 64 + 32 + dq * 4);
                ull cd;
                cd = pack2(c0.x, c0.x);
                ffma2(acc[0],  cd, hA.x); ffma2(acc[1],  cd, hA.y);
                ffma2(acc[2],  cd, hB.x); ffma2(acc[3],  cd, hB.y);
                cd = pack2(c0.y, c0.y);
                ffma2(acc[4],  cd, hA.x); ffma2(acc[5],  cd, hA.y);
                ffma2(acc[6],  cd, hB.x); ffma2(acc[7],  cd, hB.y);
                cd = pack2(c0.z, c0.z);
                ffma2(acc[8],  cd, hA.x); ffma2(acc[9],  cd, hA.y);
                ffma2(acc[10], cd, hB.x); ffma2(acc[11], cd, hB.y);
                cd = pack2(c0.w, c0.w);
                ffma2(acc[12], cd, hA.x); ffma2(acc[13], cd, hA.y);
                ffma2(acc[14], cd, hB.x); ffma2(acc[15], cd, hB.y);
                cd = pack2(c1.x, c1.x);
                ffma2(acc[16], cd, hA.x); ffma2(acc[17], cd, hA.y);
                ffma2(acc[18], cd, hB.x); ffma2(acc[19], cd, hB.y);
                cd = pack2(c1.y, c1.y);
                ffma2(acc[20], cd, hA.x); ffma2(acc[21], cd, hA.y);
                ffma2(acc[22], cd, hB.x); ffma2(acc[23], cd, hB.y);
                cd = pack2(c1.z, c1.z);
                ffma2(acc[24], cd, hA.x); ffma2(acc[25], cd, hA.y);
                ffma2(acc[26], cd, hB.x); ffma2(acc[27], cd, hB.y);
                cd = pack2(c1.w, c1.w);
                ffma2(acc[28], cd, hA.x); ffma2(acc[29], cd, hA.y);
                ffma2(acc[30], cd, hB.x); ffma2(acc[31], cd, hB.y);
            }
        }

        // ---- stage+gen next chunk into other buffer ----
        if (cg < 3) {
            int nbuf = buf ^ 1;
            float* hb = hwp_s + (gid * 2 + nbuf) * 2048;
            #pragma unroll
            for (int t = 0; t < 4; ++t) {
                int i = wt + t * 128;
                int m = i >> 4, d16 = i & 15;
                *(float4*)(hb + m * 64 + (d16 & 1) * 32 + (d16 >> 1) * 4) = pf_hw[t];
            }
            float* cb = coef_s + (gid * 2 + nbuf) * 4096;
            float2 t1e1 = t1e1_s[wt];
            int lc = gid * 4 + cg + 1;
            #pragma unroll 8
            for (int m = 0; m < 32; ++m) {
                float2 te = te_s[lc * 32 + m];
                bool p = ((pf_aw >> m) & 1u) && (t1e1.x + te.x > 0.f);
                float cf = p ? fmaf(t1e1.y, te.y, -1.f) : 0.f;
                zpart += cf;
                cb[m * 128 + wt] = cf;
            }
        }
        asm volatile("bar.sync %0, %1;" :: "r"(gid + 1), "r"(128) : "memory");
    }

    // ---- dump all groups' accumulators + z ----
    z_s[gid * 128 + wt] = zpart;
    {
        ull* dump = (ull*)(smem + SM_COEF) + (size_t)gid * 4096 + wt * 32;
        #pragma unroll
        for (int i = 0; i < 32; ++i) dump[i] = acc[i];
    }
    __syncthreads();

    // ---- parallel cross-group reduction: 512 threads, each 2 rows x 8 cols --
    {
        int p = tid >> 2, q = tid & 3;          // p = (nq,dq) pair, q = row sub
        int pnq = p >> 3, pdq = p & 7;
        ull r[8];
        const ull* base = (const ull*)(smem + SM_COEF);
        #pragma unroll
        for (int k = 0; k < 8; ++k) r[k] = base[(size_t)p * 32 + q * 8 + k];
        #pragma unroll
        for (int g = 1; g < 4; ++g) {
            const ull* src = base + (size_t)g * 4096 + p * 32 + q * 8;
            #pragma unroll
            for (int k = 0; k < 8; ++k) r[k] = addf2(r[k], src[k]);
        }
        float* npbase = g_nP + (size_t)ms * (BB * NN * DD);
        #pragma unroll
        for (int rr = 0; rr < 2; ++rr) {
            int n_local = pnq * 8 + q * 2 + rr;
            float x0, x1, x2, x3, x4, x5, x6, x7;
            unpack2(r[rr * 4 + 0], x0, x1);
            unpack2(r[rr * 4 + 1], x2, x3);
            unpack2(r[rr * 4 + 2], x4, x5);
            unpack2(r[rr * 4 + 3], x6, x7);
            float* np = npbase + (size_t)(b * NN + nbase + n_local) * 64 + pdq * 8;
            ((float4*)np)[0] = make_float4(x0, x1, x2, x3);
            ((float4*)np)[1] = make_float4(x4, x5, x6, x7);
        }
        if (tid < 128) {
            float zv = z_s[tid] + z_s[128 + tid] + z_s[256 + tid] + z_s[384 + tid];
            g_zP[ms * (BB * NN) + b * NN + nbase + tid] = zv;
        }
    }

    // ---- last-arriver combine (replaces epi kernel) ----
    __threadfence();
    __syncthreads();
    if (tid == 0) sh_who = atomicAdd(&g_tilecnt[pair * 8 + nt], 1);
    __syncthreads();
    if (sh_who == 1) {
        int row = tid >> 2, seg = tid & 3;      // 128 rows x 4 col-segments of 16
        if (nbase + row < cnt) {
            int gpos = b * NN + nbase + row;
            int ridx = idx_s[row];
            float Z = (float)NN + g_zP[gpos] + g_zP[BB * NN + gpos];
            float invZ = __fdividef(1.f, Z);
            const float4* p0 = (const float4*)(g_nP + (size_t)gpos * 64) + seg * 4;
            const float4* p1 = (const float4*)(g_nP + (size_t)(BB * NN) * 64 + (size_t)gpos * 64) + seg * 4;
            const float4* sl = (const float4*)(g_Sall3 + li * (BB * DD) + b * 64) + seg * 4;
            float4* ho = (float4*)(g_h + ((size_t)b * NN + ridx) * 64) + seg * 4;
            #pragma unroll
            for (int k = 0; k < 4; ++k) {
                float4 a = p0[k], c = p1[k], s = sl[k];
                ho[k] = make_float4((s.x + a.x + c.x) * invZ,
                                    (s.y + a.y + c.y) * invZ,
                                    (s.z + a.z + c.z) * invZ,
                                    (s.w + a.w + c.w) * invZ);
            }
        }
    }
}

// ---------------- kernel 5: masked attention pool + BN-MLP head -------------
__global__ void __launch_bounds__(256) head_kernel(
    const float* __restrict__ root_list, const float* __restrict__ P,
    const float* __restrict__ pW1, const float* __restrict__ pb1,
    const float* __restrict__ g1,  const float* __restrict__ be1,
    const float* __restrict__ m1,  const float* __restrict__ v1,
    const float* __restrict__ pW2, const float* __restrict__ pb2,
    const float* __restrict__ g2,  const float* __restrict__ be2,
    const float* __restrict__ m2,  const float* __restrict__ v2,
    const float* __restrict__ pW3, const float* __restrict__ pb3,
    float* __restrict__ out) {

    __shared__ float  sh_w[NN];
    __shared__ float  sh_red[256];
    __shared__ float4 sh_part[16 * 16];
    __shared__ float  sh_pool[64];
    __shared__ float  sh_x1[128];
    __shared__ float  sh_x2[64];
    __shared__ float4 sh_P[16];

    int b = blockIdx.x;
    int tid = threadIdx.x;
    if (tid < 16) sh_P[tid] = ((const float4*)P)[tid];
    __syncthreads();

    float wsum = 0.f;
    for (int n = tid; n < NN; n += 256) {
        const float4* hr = (const float4*)(g_h + ((size_t)b * NN + n) * 64);
        float s = 0.f;
        #pragma unroll
        for (int k = 0; k < 16; ++k) {
            float4 h4 = hr[k]; float4 p4 = sh_P[k];
            s = fmaf(h4.x, p4.x, s);
            s = fmaf(h4.y, p4.y, s);
            s = fmaf(h4.z, p4.z, s);
            s = fmaf(h4.w, p4.w, s);
        }
        s = fmaxf(s, 0.f);
        float root = root_list[b * (4 * NN) + 1 * NN + n];
        float wv = (root > 0.f) ? __expf(s) : 0.f;
        sh_w[n] = wv;
        wsum += wv;
    }
    sh_red[tid] = wsum;
    __syncthreads();
    for (int o = 128; o > 0; o >>= 1) {
        if (tid < o) sh_red[tid] += sh_red[tid + o];
        __syncthreads();
    }
    float invw = __fdividef(1.f, sh_red[0]);

    {
        int dq = tid & 15, grp = tid >> 4;     // 16 groups of 16
        const float4* hb = (const float4*)(g_h + (size_t)b * NN * 64);
        float4 a = make_float4(0.f, 0.f, 0.f, 0.f);
        #pragma unroll 4
        for (int it = 0; it < 64; ++it) {
            int n = grp + it * 16;
            float wv = sh_w[n];
            float4 h4 = hb[n * 16 + dq];
            a.x = fmaf(wv, h4.x, a.x);
            a.y = fmaf(wv, h4.y, a.y);
            a.z = fmaf(wv, h4.z, a.z);
            a.w = fmaf(wv, h4.w, a.w);
        }
        sh_part[grp * 16 + dq] = a;
    }
    __syncthreads();
    if (tid < 64) {
        int dq = tid >> 2, comp = tid & 3;
        float acc = 0.f;
        #pragma unroll
        for (int g = 0; g < 16; ++g) {
            const float* p = (const float*)&sh_part[g * 16 + dq];
            acc += p[comp];
        }
        sh_pool[dq * 4 + comp] = acc * invw;
    }
    __syncthreads();

    if (tid < 128) {
        float acc = pb1[tid];
        #pragma unroll 8
        for (int k = 0; k < 64; ++k) acc = fmaf(sh_pool[k], pW1[k * 128 + tid], acc);
        float bnv = (acc - m1[tid]) * rsqrtf(v1[tid] + BN_EPS) * g1[tid] + be1[tid];
        sh_x1[tid] = fmaxf(bnv, 0.f);
    }
    __syncthreads();

    if (tid < 64) {
        float acc = pb2[tid];
        #pragma unroll 8
        for (int k = 0; k < 128; ++k) acc = fmaf(sh_x1[k], pW2[k * 64 + tid], acc);
        float bnv = (acc - m2[tid]) * rsqrtf(v2[tid] + BN_EPS) * g2[tid] + be2[tid];
        sh_x2[tid] = fmaxf(bnv, 0.f);
    }
    __syncthreads();

    if (tid == 0) {
        float l0 = pb3[0], l1 = pb3[1];
        #pragma unroll 8
        for (int k = 0; k < 64; ++k) {
            l0 = fmaf(sh_x2[k], pW3[k * 2 + 0], l0);
            l1 = fmaf(sh_x2[k], pW3[k * 2 + 1], l1);
        }
        l0 = fmaxf(l0, 0.f); l1 = fmaxf(l1, 0.f);
        float mx = fmaxf(l0, l1);
        float e0 = __expf(l0 - mx), e1 = __expf(l1 - mx);
        float inv = __fdividef(1.f, e0 + e1);
        out[b * 2 + 0] = e0 * inv;
        out[b * 2 + 1] = e1 * inv;
    }
}

// ---------------- launch -----------------------------------------------------
extern "C" void kernel_launch(void* const* d_in, const int* in_sizes, int n_in,
                              void* d_out, int out_size) {
    const int*   adj       = (const int*)  d_in[0];
    const float* X         = (const float*)d_in[1];
    const float* root_list = (const float*)d_in[2];
    const float* W0        = (const float*)d_in[3];
    const float* Wl        = (const float*)d_in[4];
    const float* a1l       = (const float*)d_in[5];
    const float* a2l       = (const float*)d_in[6];
    const float* P         = (const float*)d_in[7];
    const float* pW1 = (const float*)d_in[8];  const float* pb1 = (const float*)d_in[9];
    const float* g1  = (const float*)d_in[10]; const float* be1 = (const float*)d_in[11];
    const float* m1  = (const float*)d_in[12]; const float* v1  = (const float*)d_in[13];
    const float* pW2 = (const float*)d_in[14]; const float* pb2 = (const float*)d_in[15];
    const float* g2  = (const float*)d_in[16]; const float* be2 = (const float*)d_in[17];
    const float* m2  = (const float*)d_in[18]; const float* v2  = (const float*)d_in[19];
    const float* pW3 = (const float*)d_in[20]; const float* pb3 = (const float*)d_in[21];
    float* out = (float*)d_out;

    cudaFuncSetAttribute(attn_kernel, cudaFuncAttributeMaxDynamicSharedMemorySize,
                         SM_ATTN_TOTAL);

    compact_kernel<<<32, 32>>>(root_list, 0);
    compact_kernel<<<16, 32>>>(root_list, 32);
    pack_adj_kernel<<<BB * 16, 256>>>(adj);
    input_proj_kernel<<<BB * NN / 64, 256>>>(X, W0);

    for (int li = 0; li < 3; ++li) {
        hw_kernel<<<BB * NN / 64, 256>>>(Wl, a1l, a2l, li);
        attn_kernel<<<BB * 16, 512, SM_ATTN_TOTAL>>>(li);
    }

    head_kernel<<<BB, 256>>>(root_list, P,
                             pW1, pb1, g1, be1, m1, v1,
                             pW2, pb2, g2, be2, m2, v2,
                             pW3, pb3, out);
}

// round 12
// speedup vs baseline: 1.0761x; 1.0761x over previous
#include <cuda_runtime.h>
#include <cstdint>

#define BB 16
#define NN 1024
#define DD 64
#define FIN 80
#define BN_EPS 1e-5f

typedef unsigned long long ull;

// ---------------- scratch globals -------------------------------------------
__device__ float    g_h[BB*NN*DD];          // node features fp32
__device__ float    g_hW[BB*NN*DD];         // relu(h @ Wl)
__device__ float2   g_t1e1[BB*NN];          // (t1, exp(t1))
__device__ float2   g_te2[BB*NN];           // (t2, exp(t2))
__device__ unsigned g_adjT[BB*32*NN];       // transposed bitmask [b][word][n]
__device__ float    g_Sall3[3*BB*DD];       // per-layer column sums of hW
__device__ int      g_idx[3*BB*NN];         // active-row indices per (layer,b)
__device__ int      g_cnt[3*BB];            // active-row counts
__device__ float    g_nP[2*BB*NN*DD];       // m-split partial numerators
__device__ float    g_zP[2*BB*NN];          // m-split partial Z
__device__ int      g_tilecnt[3*BB*8];      // per-tile arrival counters

// ---------------- packed f32x2 helpers --------------------------------------
__device__ __forceinline__ ull pack2(float x, float y) {
    ull r;
    asm("mov.b64 %0, {%1, %2};" : "=l"(r) : "f"(x), "f"(y));
    return r;
}
__device__ __forceinline__ void unpack2(ull v, float &x, float &y) {
    asm("mov.b64 {%0, %1}, %2;" : "=f"(x), "=f"(y) : "l"(v));
}
__device__ __forceinline__ void ffma2(ull &d, ull a, ull b) {
    asm("fma.rn.f32x2 %0, %1, %2, %0;" : "+l"(d) : "l"(a), "l"(b));
}
__device__ __forceinline__ ull addf2(ull a, ull b) {
    ull r;
    asm("add.rn.f32x2 %0, %1, %2;" : "=l"(r) : "l"(a), "l"(b));
    return r;
}

// ---------------- kernel 0: compact active rows per (layer, b) --------------
__global__ void __launch_bounds__(32) compact_kernel(const float* __restrict__ root_list,
                                                     int pair0) {
    int pair = pair0 + blockIdx.x;         // li*16 + b
    int li = pair >> 4, b = pair & 15;
    int lane = threadIdx.x;
    int rootLayer = 3 - li;
    const float* r = root_list + b * (4 * NN) + rootLayer * NN;
    int* idx = g_idx + (size_t)pair * NN;
    if (lane < 8) g_tilecnt[pair * 8 + lane] = 0;
    int cnt = 0;
    for (int c = 0; c < 32; ++c) {
        int n = c * 32 + lane;
        bool a = r[n] > 0.f;
        unsigned m = __ballot_sync(0xffffffffu, a);
        int pos = cnt + __popc(m & ((1u << lane) - 1u));
        if (a) idx[pos] = n;
        cnt += __popc(m);
    }
    for (int i = cnt + lane; i < NN; i += 32) idx[i] = 0;
    if (lane == 0) g_cnt[pair] = cnt;
}

// ---------------- kernel 1: pack adj (transposed bitmask) + zero Sall -------
__global__ void __launch_bounds__(256) pack_adj_kernel(const int* __restrict__ adj) {
    __shared__ unsigned tw[32 * 64];       // [word][n_local]
    int b  = blockIdx.x >> 4;
    int nt = blockIdx.x & 15;
    int tid = threadIdx.x;
    int w   = tid >> 5;
    int lane = tid & 31;

    if (blockIdx.x == 0) {
        for (int i = tid; i < 3 * BB * DD; i += 256) g_Sall3[i] = 0.f;
    }

    for (int j = 0; j < 8; ++j) {
        int nl = w * 8 + j;
        const int* rowp = adj + ((size_t)(b * NN + nt * 64 + nl)) * NN;
        #pragma unroll 4
        for (int c = 0; c < 32; ++c) {
            int v = rowp[c * 32 + lane];
            unsigned m = __ballot_sync(0xffffffffu, v > 0);
            if (lane == 0) tw[c * 64 + nl] = m;
        }
    }
    __syncthreads();
    for (int i = tid; i < 2048; i += 256) {
        int c = i >> 6, nl = i & 63;
        g_adjT[(size_t)(b * 32 + c) * NN + nt * 64 + nl] = tw[i];
    }
}

// ---------------- kernel 2: h = relu(X @ W0) (uncapped regs, no spills) -----
__global__ void __launch_bounds__(256) input_proj_kernel(const float* __restrict__ X,
                                                         const float* __restrict__ W0) {
    __shared__ float  xs[64 * FIN];
    __shared__ float2 wp[FIN * 32];
    int tid = threadIdx.x;
    int rowbase = blockIdx.x * 64;

    const float4* xsrc = (const float4*)(X + (size_t)rowbase * FIN);
    float4* xdst = (float4*)xs;
    #pragma unroll
    for (int t = 0; t < 5; ++t) xdst[tid + t * 256] = xsrc[tid + t * 256];

    for (int idx = tid; idx < FIN * 32; idx += 256) {
        int k = idx >> 5, l = idx & 31;
        wp[idx] = make_float2(W0[k * 64 + l], W0[k * 64 + l + 32]);
    }
    __syncthreads();

    int w = tid >> 5, lane = tid & 31;
    for (int j = 0; j < 8; ++j) {
        int row = w * 8 + j;
        const float* xr = xs + row * FIN;
        float a0 = 0.f, a1 = 0.f;
        #pragma unroll
        for (int k = 0; k < FIN; k += 4) {
            float4 x4 = *(const float4*)(xr + k);
            float2 w0 = wp[(k + 0) * 32 + lane];
            float2 w1 = wp[(k + 1) * 32 + lane];
            float2 w2 = wp[(k + 2) * 32 + lane];
            float2 w3 = wp[(k + 3) * 32 + lane];
            a0 = fmaf(x4.x, w0.x, a0); a1 = fmaf(x4.x, w0.y, a1);
            a0 = fmaf(x4.y, w1.x, a0); a1 = fmaf(x4.y, w1.y, a1);
            a0 = fmaf(x4.z, w2.x, a0); a1 = fmaf(x4.z, w2.y, a1);
            a0 = fmaf(x4.w, w3.x, a0); a1 = fmaf(x4.w, w3.y, a1);
        }
        int gr = rowbase + row;
        g_h[gr * 64 + lane]      = fmaxf(a0, 0.f);
        g_h[gr * 64 + lane + 32] = fmaxf(a1, 0.f);
    }
}

// ---- kernel 3: hW = relu(h@Wl); t1/t2/exp; Sall; 2 CTAs/SM -----------------
__global__ void __launch_bounds__(256, 2) hw_kernel(const float* __restrict__ Wl,
                                                    const float* __restrict__ a1l,
                                                    const float* __restrict__ a2l,
                                                    int li) {
    __shared__ float  hs[64 * 64];
    __shared__ float2 wp[64 * 32];
    __shared__ float2 pt[64 * 9];
    int tid = threadIdx.x;
    int rowbase = blockIdx.x * 64;
    int b = rowbase >> 10;

    const float4* hsrc = (const float4*)(g_h + (size_t)rowbase * 64);
    float4* hdst = (float4*)hs;
    #pragma unroll
    for (int t = 0; t < 4; ++t) hdst[tid + t * 256] = hsrc[tid + t * 256];

    const float* W = Wl + li * 4096;
    for (int idx = tid; idx < 2048; idx += 256) {
        int k = idx >> 5, l = idx & 31;
        wp[idx] = make_float2(W[k * 64 + l], W[k * 64 + l + 32]);
    }
    __syncthreads();

    int w = tid >> 5, lane = tid & 31;
    float a1lo = a1l[li * 64 + lane], a1hi = a1l[li * 64 + lane + 32];
    float a2lo = a2l[li * 64 + lane], a2hi = a2l[li * 64 + lane + 32];
    float s0 = 0.f, s1 = 0.f;

    #pragma unroll
    for (int jg = 0; jg < 4; ++jg) {
        int row0 = w * 8 + jg * 2;
        const float* hr0 = hs + (row0 + 0) * 64;
        const float* hr1 = hs + (row0 + 1) * 64;
        float acc[2][2];
        acc[0][0] = 0.f; acc[0][1] = 0.f;
        acc[1][0] = 0.f; acc[1][1] = 0.f;

        #pragma unroll
        for (int k = 0; k < 64; k += 4) {
            float2 w0 = wp[(k + 0) * 32 + lane];
            float2 w1 = wp[(k + 1) * 32 + lane];
            float2 w2 = wp[(k + 2) * 32 + lane];
            float2 w3 = wp[(k + 3) * 32 + lane];
            float4 h0 = *(const float4*)(hr0 + k);
            float4 h1 = *(const float4*)(hr1 + k);
            acc[0][0] = fmaf(h0.x, w0.x, acc[0][0]); acc[0][1] = fmaf(h0.x, w0.y, acc[0][1]);
            acc[0][0] = fmaf(h0.y, w1.x, acc[0][0]); acc[0][1] = fmaf(h0.y, w1.y, acc[0][1]);
            acc[0][0] = fmaf(h0.z, w2.x, acc[0][0]); acc[0][1] = fmaf(h0.z, w2.y, acc[0][1]);
            acc[0][0] = fmaf(h0.w, w3.x, acc[0][0]); acc[0][1] = fmaf(h0.w, w3.y, acc[0][1]);
            acc[1][0] = fmaf(h1.x, w0.x, acc[1][0]); acc[1][1] = fmaf(h1.x, w0.y, acc[1][1]);
            acc[1][0] = fmaf(h1.y, w1.x, acc[1][0]); acc[1][1] = fmaf(h1.y, w1.y, acc[1][1]);
            acc[1][0] = fmaf(h1.z, w2.x, acc[1][0]); acc[1][1] = fmaf(h1.z, w2.y, acc[1][1]);
            acc[1][0] = fmaf(h1.w, w3.x, acc[1][0]); acc[1][1] = fmaf(h1.w, w3.y, acc[1][1]);
        }

        #pragma unroll
        for (int r = 0; r < 2; ++r) {
            float acc0 = fmaxf(acc[r][0], 0.f);
            float acc1 = fmaxf(acc[r][1], 0.f);
            int row = row0 + r;
            int gr = rowbase + row;
            g_hW[gr * 64 + lane]      = acc0;
            g_hW[gr * 64 + lane + 32] = acc1;
            s0 += acc0; s1 += acc1;

            float p1 = fmaf(acc1, a1hi, acc0 * a1lo);
            float p2 = fmaf(acc1, a2hi, acc0 * a2lo);
            p1 += __shfl_down_sync(0xffffffffu, p1, 16);
            p2 += __shfl_down_sync(0xffffffffu, p2, 16);
            p1 += __shfl_down_sync(0xffffffffu, p1, 8);
            p2 += __shfl_down_sync(0xffffffffu, p2, 8);
            if (lane < 8) pt[row * 9 + lane] = make_float2(p1, p2);
        }
    }
    float* sall = g_Sall3 + li * (BB * DD);
    atomicAdd(&sall[b * 64 + lane],      s0);
    atomicAdd(&sall[b * 64 + lane + 32], s1);

    __syncthreads();
    if (tid < 64) {
        int row = tid;
        float p1 = 0.f, p2 = 0.f;
        #pragma unroll
        for (int k = 0; k < 8; ++k) {
            float2 q = pt[row * 9 + k];
            p1 += q.x; p2 += q.y;
        }
        int gr = rowbase + row;
        g_t1e1[gr] = make_float2(p1, __expf(p1));
        g_te2[gr]  = make_float2(p2, __expf(p2));
    }
}

// ---------------- kernel 4: compacted + m-split attention (FFMA2, 8n x 8d) --
// Fused: parallel cross-group reduction + last-arriver combine (no epi kernel).
#define SM_COEF   0          // f32[4][2][32*128] = 131072 (also acc dump: 4x32KB)
#define SM_HWP    131072     // f32[4][2][32*64]  = 65536
#define SM_TE     196608     // float2[512]       = 4096
#define SM_T1E1   204800     // float2[128]       = 1024
#define SM_IDX    205824     // int[128]          = 512
#define SM_Z      206592     // f32[4][128]       = 2048
#define SM_ATTN_TOTAL 208640

__global__ void __launch_bounds__(512, 1) attn_kernel(int li) {
    extern __shared__ char smem[];
    float*  coef_s = (float*)(smem + SM_COEF);
    float*  hwp_s  = (float*)(smem + SM_HWP);
    float2* te_s   = (float2*)(smem + SM_TE);
    float2* t1e1_s = (float2*)(smem + SM_T1E1);
    int*    idx_s  = (int*)(smem + SM_IDX);
    float*  z_s    = (float*)(smem + SM_Z);
    __shared__ int sh_who;

    int tid = threadIdx.x;
    int bx  = blockIdx.x;
    int b   = bx >> 4;
    int nt  = (bx >> 1) & 7;
    int ms  = bx & 1;
    int nbase = nt * 128;
    int pair = li * 16 + b;
    int cnt = g_cnt[pair];
    if (nbase >= cnt) return;

    int gid = tid >> 7;                  // m-group 0..3
    int wt  = tid & 127;                 // thread within group
    int nq = wt >> 3;                    // 0..15 -> n rows nq*8..+7
    int dq = wt & 7;                     // 0..7  -> d cols dq*8..+7

    const float4*   hwbase = (const float4*)(g_hW + (size_t)b * NN * DD);
    const float2*   te_g   = g_te2 + b * NN;
    const unsigned* awcol  = g_adjT + (size_t)b * 32 * NN;

    int ri = g_idx[(size_t)pair * NN + nbase + wt];

    // ---- prefetch chunk 0 of this group ----
    unsigned pf_aw;
    float4 pf_hw[4];
    {
        int c = ms * 16 + gid * 4;
        pf_aw = awcol[(size_t)c * NN + ri];
        #pragma unroll
        for (int t = 0; t < 4; ++t) {
            int i = wt + t * 128;
            pf_hw[t] = hwbase[(c * 32 + (i >> 4)) * 16 + (i & 15)];
        }
    }

    // ---- CTA-wide staging ----
    te_s[tid] = te_g[ms * 512 + tid];
    if (tid < 128) {
        idx_s[tid]  = ri;
        t1e1_s[tid] = g_t1e1[b * NN + ri];
    }
    __syncthreads();

    float zpart = 0.f;

    // stage+gen chunk 0 into buf 0
    {
        float* hb = hwp_s + (gid * 2 + 0) * 2048;
        #pragma unroll
        for (int t = 0; t < 4; ++t) {
            int i = wt + t * 128;
            int m = i >> 4, d16 = i & 15;
            *(float4*)(hb + m * 64 + (d16 & 1) * 32 + (d16 >> 1) * 4) = pf_hw[t];
        }
        float* cb = coef_s + (gid * 2 + 0) * 4096;
        float2 t1e1 = t1e1_s[wt];
        int lc = gid * 4;
        #pragma unroll 8
        for (int m = 0; m < 32; ++m) {
            float2 te = te_s[lc * 32 + m];
            bool p = ((pf_aw >> m) & 1u) && (t1e1.x + te.x > 0.f);
            float cf = p ? fmaf(t1e1.y, te.y, -1.f) : 0.f;
            zpart += cf;
            cb[m * 128 + wt] = cf;
        }
    }
    asm volatile("bar.sync %0, %1;" :: "r"(gid + 1), "r"(128) : "memory");

    ull acc[32];
    #pragma unroll
    for (int i = 0; i < 32; ++i) acc[i] = 0ull;

    #pragma unroll 1
    for (int cg = 0; cg < 4; ++cg) {
        int buf = cg & 1;

        if (cg < 3) {
            int c = ms * 16 + gid * 4 + cg + 1;
            pf_aw = awcol[(size_t)c * NN + idx_s[wt]];
            #pragma unroll
            for (int t = 0; t < 4; ++t) {
                int i = wt + t * 128;
                pf_hw[t] = hwbase[(c * 32 + (i >> 4)) * 16 + (i & 15)];
            }
        }

        // ---- matmul on current buffer ----
        {
            const float* cb = coef_s + (gid * 2 + buf) * 4096;
            const float* hb = hwp_s + (gid * 2 + buf) * 2048;
            #pragma unroll 4
            for (int m = 0; m < 32; ++m) {
                float4 c0 = *(const float4*)(cb + m * 128 + nq * 8);
                float4 c1 = *(const float4*)(cb + m * 128 + nq * 8 + 4);
                ulonglong2 hA = *(const ulonglong2*)(hb + m * 64 + dq * 4);
                ulonglong2 hB = *(const ulonglong2*)(hb + m * 64 + 32 + dq * 4);
                ull cd;
                cd = pack2(c0.x, c0.x);
                ffma2(acc[0],  cd, hA.x); ffma2(acc[1],  cd, hA.y);
                ffma2(acc[2],  cd, hB.x); ffma2(acc[3],  cd, hB.y);
                cd = pack2(c0.y, c0.y);
                ffma2(acc[4],  cd, hA.x); ffma2(acc[5],  cd, hA.y);
                ffma2(acc[6],  cd, hB.x); ffma2(acc[7],  cd, hB.y);
                cd = pack2(c0.z, c0.z);
                ffma2(acc[8],  cd, hA.x); ffma2(acc[9],  cd, hA.y);
                ffma2(acc[10], cd, hB.x); ffma2(acc[11], cd, hB.y);
                cd = pack2(c0.w, c0.w);
                ffma2(acc[12], cd, hA.x); ffma2(acc[13], cd, hA.y);
                ffma2(acc[14], cd, hB.x); ffma2(acc[15], cd, hB.y);
                cd = pack2(c1.x, c1.x);
                ffma2(acc[16], cd, hA.x); ffma2(acc[17], cd, hA.y);
                ffma2(acc[18], cd, hB.x); ffma2(acc[19], cd, hB.y);
                cd = pack2(c1.y, c1.y);
                ffma2(acc[20], cd, hA.x); ffma2(acc[21], cd, hA.y);
                ffma2(acc[22], cd, hB.x); ffma2(acc[23], cd, hB.y);
                cd = pack2(c1.z, c1.z);
                ffma2(acc[24], cd, hA.x); ffma2(acc[25], cd, hA.y);
                ffma2(acc[26], cd, hB.x); ffma2(acc[27], cd, hB.y);
                cd = pack2(c1.w, c1.w);
                ffma2(acc[28], cd, hA.x); ffma2(acc[29], cd, hA.y);
                ffma2(acc[30], cd, hB.x); ffma2(acc[31], cd, hB.y);
            }
        }

        // ---- stage+gen next chunk into other buffer ----
        if (cg < 3) {
            int nbuf = buf ^ 1;
            float* hb = hwp_s + (gid * 2 + nbuf) * 2048;
            #pragma unroll
            for (int t = 0; t < 4; ++t) {
                int i = wt + t * 128;
                int m = i >> 4, d16 = i & 15;
                *(float4*)(hb + m * 64 + (d16 & 1) * 32 + (d16 >> 1) * 4) = pf_hw[t];
            }
            float* cb = coef_s + (gid * 2 + nbuf) * 4096;
            float2 t1e1 = t1e1_s[wt];
            int lc = gid * 4 + cg + 1;
            #pragma unroll 8
            for (int m = 0; m < 32; ++m) {
                float2 te = te_s[lc * 32 + m];
                bool p = ((pf_aw >> m) & 1u) && (t1e1.x + te.x > 0.f);
                float cf = p ? fmaf(t1e1.y, te.y, -1.f) : 0.f;
                zpart += cf;
                cb[m * 128 + wt] = cf;
            }
        }
        asm volatile("bar.sync %0, %1;" :: "r"(gid + 1), "r"(128) : "memory");
    }

    // ---- dump all groups' accumulators + z ----
    z_s[gid * 128 + wt] = zpart;
    {
        ull* dump = (ull*)(smem + SM_COEF) + (size_t)gid * 4096 + wt * 32;
        #pragma unroll
        for (int i = 0; i < 32; ++i) dump[i] = acc[i];
    }
    __syncthreads();

    // ---- parallel cross-group reduction: 512 threads, each 2 rows x 8 cols --
    {
        int p = tid >> 2, q = tid & 3;          // p = (nq,dq) pair, q = row sub
        int pnq = p >> 3, pdq = p & 7;
        ull r[8];
        const ull* base = (const ull*)(smem + SM_COEF);
        #pragma unroll
        for (int k = 0; k < 8; ++k) r[k] = base[(size_t)p * 32 + q * 8 + k];
        #pragma unroll
        for (int g = 1; g < 4; ++g) {
            const ull* src = base + (size_t)g * 4096 + p * 32 + q * 8;
            #pragma unroll
            for (int k = 0; k < 8; ++k) r[k] = addf2(r[k], src[k]);
        }
        float* npbase = g_nP + (size_t)ms * (BB * NN * DD);
        #pragma unroll
        for (int rr = 0; rr < 2; ++rr) {
            int n_local = pnq * 8 + q * 2 + rr;
            float x0, x1, x2, x3, x4, x5, x6, x7;
            unpack2(r[rr * 4 + 0], x0, x1);
            unpack2(r[rr * 4 + 1], x2, x3);
            unpack2(r[rr * 4 + 2], x4, x5);
            unpack2(r[rr * 4 + 3], x6, x7);
            float* np = npbase + (size_t)(b * NN + nbase + n_local) * 64 + pdq * 8;
            ((float4*)np)[0] = make_float4(x0, x1, x2, x3);
            ((float4*)np)[1] = make_float4(x4, x5, x6, x7);
        }
        if (tid < 128) {
            float zv = z_s[tid] + z_s[128 + tid] + z_s[256 + tid] + z_s[384 + tid];
            g_zP[ms * (BB * NN) + b * NN + nbase + tid] = zv;
        }
    }

    // ---- last-arriver combine (replaces epi kernel) ----
    __threadfence();
    __syncthreads();
    if (tid == 0) sh_who = atomicAdd(&g_tilecnt[pair * 8 + nt], 1);
    __syncthreads();
    if (sh_who == 1) {
        int row = tid >> 2, seg = tid & 3;      // 128 rows x 4 col-segments of 16
        if (nbase + row < cnt) {
            int gpos = b * NN + nbase + row;
            int ridx = idx_s[row];
            float Z = (float)NN + g_zP[gpos] + g_zP[BB * NN + gpos];
            float invZ = __fdividef(1.f, Z);
            const float4* p0 = (const float4*)(g_nP + (size_t)gpos * 64) + seg * 4;
            const float4* p1 = (const float4*)(g_nP + (size_t)(BB * NN) * 64 + (size_t)gpos * 64) + seg * 4;
            const float4* sl = (const float4*)(g_Sall3 + li * (BB * DD) + b * 64) + seg * 4;
            float4* ho = (float4*)(g_h + ((size_t)b * NN + ridx) * 64) + seg * 4;
            #pragma unroll
            for (int k = 0; k < 4; ++k) {
                float4 a = p0[k], c = p1[k], s = sl[k];
                ho[k] = make_float4((s.x + a.x + c.x) * invZ,
                                    (s.y + a.y + c.y) * invZ,
                                    (s.z + a.z + c.z) * invZ,
                                    (s.w + a.w + c.w) * invZ);
            }
        }
    }
}

// ---------------- kernel 5: masked attention pool + BN-MLP head -------------
__global__ void __launch_bounds__(256) head_kernel(
    const float* __restrict__ root_list, const float* __restrict__ P,
    const float* __restrict__ pW1, const float* __restrict__ pb1,
    const float* __restrict__ g1,  const float* __restrict__ be1,
    const float* __restrict__ m1,  const float* __restrict__ v1,
    const float* __restrict__ pW2, const float* __restrict__ pb2,
    const float* __restrict__ g2,  const float* __restrict__ be2,
    const float* __restrict__ m2,  const float* __restrict__ v2,
    const float* __restrict__ pW3, const float* __restrict__ pb3,
    float* __restrict__ out) {

    __shared__ float  sh_w[NN];
    __shared__ float  sh_red[256];
    __shared__ float4 sh_part[16 * 16];
    __shared__ float  sh_pool[64];
    __shared__ float  sh_x1[128];
    __shared__ float  sh_x2[64];
    __shared__ float4 sh_P[16];

    int b = blockIdx.x;
    int tid = threadIdx.x;
    if (tid < 16) sh_P[tid] = ((const float4*)P)[tid];
    __syncthreads();

    float wsum = 0.f;
    for (int n = tid; n < NN; n += 256) {
        const float4* hr = (const float4*)(g_h + ((size_t)b * NN + n) * 64);
        float s = 0.f;
        #pragma unroll
        for (int k = 0; k < 16; ++k) {
            float4 h4 = hr[k]; float4 p4 = sh_P[k];
            s = fmaf(h4.x, p4.x, s);
            s = fmaf(h4.y, p4.y, s);
            s = fmaf(h4.z, p4.z, s);
            s = fmaf(h4.w, p4.w, s);
        }
        s = fmaxf(s, 0.f);
        float root = root_list[b * (4 * NN) + 1 * NN + n];
        float wv = (root > 0.f) ? __expf(s) : 0.f;
        sh_w[n] = wv;
        wsum += wv;
    }
    sh_red[tid] = wsum;
    __syncthreads();
    for (int o = 128; o > 0; o >>= 1) {
        if (tid < o) sh_red[tid] += sh_red[tid + o];
        __syncthreads();
    }
    float invw = __fdividef(1.f, sh_red[0]);

    {
        int dq = tid & 15, grp = tid >> 4;     // 16 groups of 16
        const float4* hb = (const float4*)(g_h + (size_t)b * NN * 64);
        float4 a = make_float4(0.f, 0.f, 0.f, 0.f);
        #pragma unroll 4
        for (int it = 0; it < 64; ++it) {
            int n = grp + it * 16;
            float wv = sh_w[n];
            float4 h4 = hb[n * 16 + dq];
            a.x = fmaf(wv, h4.x, a.x);
            a.y = fmaf(wv, h4.y, a.y);
            a.z = fmaf(wv, h4.z, a.z);
            a.w = fmaf(wv, h4.w, a.w);
        }
        sh_part[grp * 16 + dq] = a;
    }
    __syncthreads();
    if (tid < 64) {
        int dq = tid >> 2, comp = tid & 3;
        float acc = 0.f;
        #pragma unroll
        for (int g = 0; g < 16; ++g) {
            const float* p = (const float*)&sh_part[g * 16 + dq];
            acc += p[comp];
        }
        sh_pool[dq * 4 + comp] = acc * invw;
    }
    __syncthreads();

    if (tid < 128) {
        float acc = pb1[tid];
        #pragma unroll 8
        for (int k = 0; k < 64; ++k) acc = fmaf(sh_pool[k], pW1[k * 128 + tid], acc);
        float bnv = (acc - m1[tid]) * rsqrtf(v1[tid] + BN_EPS) * g1[tid] + be1[tid];
        sh_x1[tid] = fmaxf(bnv, 0.f);
    }
    __syncthreads();

    if (tid < 64) {
        float acc = pb2[tid];
        #pragma unroll 8
        for (int k = 0; k < 128; ++k) acc = fmaf(sh_x1[k], pW2[k * 64 + tid], acc);
        float bnv = (acc - m2[tid]) * rsqrtf(v2[tid] + BN_EPS) * g2[tid] + be2[tid];
        sh_x2[tid] = fmaxf(bnv, 0.f);
    }
    __syncthreads();

    if (tid == 0) {
        float l0 = pb3[0], l1 = pb3[1];
        #pragma unroll 8
        for (int k = 0; k < 64; ++k) {
            l0 = fmaf(sh_x2[k], pW3[k * 2 + 0], l0);
            l1 = fmaf(sh_x2[k], pW3[k * 2 + 1], l1);
        }
        l0 = fmaxf(l0, 0.f); l1 = fmaxf(l1, 0.f);
        float mx = fmaxf(l0, l1);
        float e0 = __expf(l0 - mx), e1 = __expf(l1 - mx);
        float inv = __fdividef(1.f, e0 + e1);
        out[b * 2 + 0] = e0 * inv;
        out[b * 2 + 1] = e1 * inv;
    }
}

// ---------------- launch -----------------------------------------------------
extern "C" void kernel_launch(void* const* d_in, const int* in_sizes, int n_in,
                              void* d_out, int out_size) {
    const int*   adj       = (const int*)  d_in[0];
    const float* X         = (const float*)d_in[1];
    const float* root_list = (const float*)d_in[2];
    const float* W0        = (const float*)d_in[3];
    const float* Wl        = (const float*)d_in[4];
    const float* a1l       = (const float*)d_in[5];
    const float* a2l       = (const float*)d_in[6];
    const float* P         = (const float*)d_in[7];
    const float* pW1 = (const float*)d_in[8];  const float* pb1 = (const float*)d_in[9];
    const float* g1  = (const float*)d_in[10]; const float* be1 = (const float*)d_in[11];
    const float* m1  = (const float*)d_in[12]; const float* v1  = (const float*)d_in[13];
    const float* pW2 = (const float*)d_in[14]; const float* pb2 = (const float*)d_in[15];
    const float* g2  = (const float*)d_in[16]; const float* be2 = (const float*)d_in[17];
    const float* m2  = (const float*)d_in[18]; const float* v2  = (const float*)d_in[19];
    const float* pW3 = (const float*)d_in[20]; const float* pb3 = (const float*)d_in[21];
    float* out = (float*)d_out;

    cudaFuncSetAttribute(attn_kernel, cudaFuncAttributeMaxDynamicSharedMemorySize,
                         SM_ATTN_TOTAL);

    compact_kernel<<<32, 32>>>(root_list, 0);
    compact_kernel<<<16, 32>>>(root_list, 32);
    pack_adj_kernel<<<BB * 16, 256>>>(adj);
    input_proj_kernel<<<BB * NN / 64, 256>>>(X, W0);

    for (int li = 0; li < 3; ++li) {
        hw_kernel<<<BB * NN / 64, 256>>>(Wl, a1l, a2l, li);
        attn_kernel<<<BB * 16, 512, SM_ATTN_TOTAL>>>(li);
    }

    head_kernel<<<BB, 256>>>(root_list, P,
                             pW1, pb1, g1, be1, m1, v1,
                             pW2, pb2, g2, be2, m2, v2,
                             pW3, pb3, out);
}